// round 12
// baseline (speedup 1.0000x reference)
#include <cuda_runtime.h>
#include <cuda_bf16.h>
#include <cstdint>

// Problem constants
#define N_NODES 100000
#define N_EDGES 1638400
#define IN_CH   128
#define HEADS   4
#define OUT_CH  32
#define OUTF    (HEADS * OUT_CH)   // 128

// Scratch (allowed: __device__ globals, no allocation)
__device__ float g_h [(size_t)N_NODES * OUTF];   // 51.2 MB, L2-resident
__device__ float g_al[(size_t)N_NODES * HEADS];
__device__ float g_ar[(size_t)N_NODES * HEADS];

// ---------------------------------------------------------------------------
// Packed f32x2 FMA (sm_100+): 2 MACs per fma-pipe issue slot.
// ---------------------------------------------------------------------------
__device__ __forceinline__ void fma_f32x2(unsigned long long& d,
                                          unsigned long long a,
                                          unsigned long long b) {
    asm("fma.rn.f32x2 %0, %1, %2, %0;" : "+l"(d) : "l"(a), "l"(b));
}
__device__ __forceinline__ unsigned long long bcast2(float v) {
    unsigned long long r;
    unsigned u = __float_as_uint(v);
    asm("mov.b64 %0, {%1, %1};" : "=l"(r) : "r"(u));
    return r;
}
__device__ __forceinline__ void unpack2(unsigned long long v, float& lo, float& hi) {
    unsigned a, b;
    asm("mov.b64 {%0, %1}, %2;" : "=r"(a), "=r"(b) : "l"(v));
    lo = __uint_as_float(a);
    hi = __uint_as_float(b);
}

// ---------------------------------------------------------------------------
// Kernel 1: h = x @ W^T + b   (M=100000, K=128, N=128)
// BM=128, BN=128, BK=32, 256 threads, 8x8 microtile, FFMA2 microloop.
// Epilogue fuses per-node attention scores alpha_l / alpha_r.
// (tcgen05 is unavailable: harness ptxas targets sm_103 without the 'a'
//  feature set — verified by round-11 compile failure.)
// ---------------------------------------------------------------------------
#define BM 128
#define BN 128
#define BK 32
#define TM 8
#define TN 8

__global__ __launch_bounds__(256, 2)
void gemm_proj_kernel(const float* __restrict__ x,
                      const float* __restrict__ W,
                      const float* __restrict__ b,
                      const float* __restrict__ att_l,
                      const float* __restrict__ att_r,
                      int nrows)
{
    __shared__ __align__(16) float Xs[BK][BM];   // k-major; reused in epilogue
    __shared__ __align__(16) float Ws[BK][BN];   // k-major; reused in epilogue

    const int tid = threadIdx.x;
    const int tx  = tid & 15;          // 0..15  (output-col group)
    const int ty  = tid >> 4;          // 0..15  (output-row group)
    const int row0 = blockIdx.x * BM;

    unsigned long long acc2[TM][TN / 2] = {};   // packed f32x2 accumulators

    for (int kt = 0; kt < IN_CH; kt += BK) {
        // ---- load X tile: rows [row0, row0+128), cols [kt, kt+32) -> Xs[k][m]
        #pragma unroll
        for (int l = tid; l < BM * (BK / 4); l += 256) {
            int m = l >> 3;
            int j = l & 7;
            int grow = row0 + m;
            float4 v = make_float4(0.f, 0.f, 0.f, 0.f);
            if (grow < nrows)
                v = *reinterpret_cast<const float4*>(x + (size_t)grow * IN_CH + kt + j * 4);
            Xs[j * 4 + 0][m] = v.x;
            Xs[j * 4 + 1][m] = v.y;
            Xs[j * 4 + 2][m] = v.z;
            Xs[j * 4 + 3][m] = v.w;
        }
        // ---- load W tile: W[o][k] -> Ws[k][o]
        #pragma unroll
        for (int l = tid; l < BN * (BK / 4); l += 256) {
            int o = l >> 3;
            int j = l & 7;
            float4 v = *reinterpret_cast<const float4*>(W + (size_t)o * IN_CH + kt + j * 4);
            Ws[j * 4 + 0][o] = v.x;
            Ws[j * 4 + 1][o] = v.y;
            Ws[j * 4 + 2][o] = v.z;
            Ws[j * 4 + 3][o] = v.w;
        }
        __syncthreads();

        #pragma unroll 8
        for (int k = 0; k < BK; k++) {
            float xf[TM];
            *reinterpret_cast<float4*>(&xf[0]) = *reinterpret_cast<const float4*>(&Xs[k][ty * TM + 0]);
            *reinterpret_cast<float4*>(&xf[4]) = *reinterpret_cast<const float4*>(&Xs[k][ty * TM + 4]);
            // adjacent float pairs in smem == f32x2 packing, read directly as u64
            ulonglong2 w01 = *reinterpret_cast<const ulonglong2*>(&Ws[k][tx * TN + 0]);
            ulonglong2 w23 = *reinterpret_cast<const ulonglong2*>(&Ws[k][tx * TN + 4]);
            unsigned long long wv[4] = { w01.x, w01.y, w23.x, w23.y };
            #pragma unroll
            for (int i = 0; i < TM; i++) {
                unsigned long long xx = bcast2(xf[i]);
                #pragma unroll
                for (int j = 0; j < TN / 2; j++)
                    fma_f32x2(acc2[i][j], xx, wv[j]);
            }
        }
        __syncthreads();   // after last iter: tiles dead, safe to reuse below
    }

    // ---- unpack accumulators
    float acc[TM][TN];
    #pragma unroll
    for (int i = 0; i < TM; i++)
        #pragma unroll
        for (int j = 0; j < TN / 2; j++)
            unpack2(acc2[i][j], acc[i][2 * j], acc[i][2 * j + 1]);

    // ---- epilogue: add bias, store h, compute per-head alpha partials
    float bias[TN], attl[TN], attr[TN];
    *reinterpret_cast<float4*>(&bias[0]) = *reinterpret_cast<const float4*>(b + tx * TN + 0);
    *reinterpret_cast<float4*>(&bias[4]) = *reinterpret_cast<const float4*>(b + tx * TN + 4);
    *reinterpret_cast<float4*>(&attl[0]) = *reinterpret_cast<const float4*>(att_l + tx * TN + 0);
    *reinterpret_cast<float4*>(&attl[4]) = *reinterpret_cast<const float4*>(att_l + tx * TN + 4);
    *reinterpret_cast<float4*>(&attr[0]) = *reinterpret_cast<const float4*>(att_r + tx * TN + 0);
    *reinterpret_cast<float4*>(&attr[4]) = *reinterpret_cast<const float4*>(att_r + tx * TN + 4);

    float* partL = &Xs[0][0];   // [128][16] partial alpha_l
    float* partR = &Ws[0][0];   // [128][16] partial alpha_r

    #pragma unroll
    for (int i = 0; i < TM; i++) {
        int lrow = ty * TM + i;
        int grow = row0 + lrow;
        float vsum[TN];
        float pl = 0.f, pr = 0.f;
        #pragma unroll
        for (int j = 0; j < TN; j++) {
            vsum[j] = acc[i][j] + bias[j];
            pl += vsum[j] * attl[j];
            pr += vsum[j] * attr[j];
        }
        partL[lrow * 16 + tx] = pl;
        partR[lrow * 16 + tx] = pr;
        if (grow < nrows) {
            *reinterpret_cast<float4*>(g_h + (size_t)grow * OUTF + tx * TN + 0) =
                make_float4(vsum[0], vsum[1], vsum[2], vsum[3]);
            *reinterpret_cast<float4*>(g_h + (size_t)grow * OUTF + tx * TN + 4) =
                make_float4(vsum[4], vsum[5], vsum[6], vsum[7]);
        }
    }
    __syncthreads();

    // reduce 4 tx-groups per (row, head)
    #pragma unroll
    for (int o = tid; o < BM * HEADS; o += 256) {
        int lrow = o >> 2;
        int head = o & 3;
        int grow = row0 + lrow;
        if (grow < nrows) {
            float sl = 0.f, sr = 0.f;
            #pragma unroll
            for (int t = 0; t < 4; t++) {
                sl += partL[lrow * 16 + head * 4 + t];
                sr += partR[lrow * 16 + head * 4 + t];
            }
            g_al[(size_t)grow * HEADS + head] = sl;
            g_ar[(size_t)grow * HEADS + head] = sr;
        }
    }
}

// ---------------------------------------------------------------------------
// Kernel 2: edge lift. Persistent grid-stride; 8 edges per warp per iter.
// g_h gathers use createpolicy L2::evict_last cache hints (legal form for
// .v4.f32 — the inline modifier form only exists for .v8.b32/.v4.b64);
// outputs use evict-first (.cs) streaming stores.
// ---------------------------------------------------------------------------
#define EPW 8   // edges per warp per iteration (N_EDGES % EPW == 0)

__device__ __forceinline__ unsigned long long mk_policy_evict_last() {
    unsigned long long pol;
    asm("createpolicy.fractional.L2::evict_last.b64 %0, 1.0;" : "=l"(pol));
    return pol;
}
__device__ __forceinline__ float4 ldg_hint(const float* p, unsigned long long pol) {
    float4 v;
    asm volatile("ld.global.nc.L2::cache_hint.v4.f32 {%0, %1, %2, %3}, [%4], %5;"
                 : "=f"(v.x), "=f"(v.y), "=f"(v.z), "=f"(v.w)
                 : "l"(p), "l"(pol));
    return v;
}

__global__ void __launch_bounds__(256, 5)
edge_lift_kernel(const int* __restrict__ src_idx,
                 const int* __restrict__ trg_idx,
                 float* __restrict__ out_alpha,
                 float* __restrict__ out_x,
                 int nedges)
{
    const int lane   = threadIdx.x & 31;
    const int nwarps = (gridDim.x * blockDim.x) >> 5;
    const int gw     = (blockIdx.x * blockDim.x + threadIdx.x) >> 5;
    const unsigned long long pol = mk_policy_evict_last();

    for (long long base = (long long)gw * EPW; base < nedges;
         base += (long long)nwarps * EPW) {

        int sidx = 0, tidx = 0;
        if (lane < EPW) {
            sidx = __ldcs(src_idx + base + lane);   // streaming: read-once
            tidx = __ldcs(trg_idx + base + lane);
        }

        int s[EPW];
        #pragma unroll
        for (int u = 0; u < EPW; u++)
            s[u] = __shfl_sync(0xffffffffu, sidx, u);

        // EPW independent gathers (MLP=EPW), L2-protected g_h
        float4 v[EPW];
        #pragma unroll
        for (int u = 0; u < EPW; u++)
            v[u] = ldg_hint(g_h + (size_t)s[u] * OUTF + lane * 4, pol);

        #pragma unroll
        for (int u = 0; u < EPW; u++)
            __stcs(reinterpret_cast<float4*>(out_x + (base + u) * OUTF + lane * 4), v[u]);

        if (lane < EPW) {
            float4 al = *reinterpret_cast<const float4*>(g_al + (size_t)sidx * HEADS);
            float4 ar = *reinterpret_cast<const float4*>(g_ar + (size_t)tidx * HEADS);
            float4 a;
            a.x = al.x + ar.x; a.x = (a.x >= 0.f) ? a.x : 0.01f * a.x;
            a.y = al.y + ar.y; a.y = (a.y >= 0.f) ? a.y : 0.01f * a.y;
            a.z = al.z + ar.z; a.z = (a.z >= 0.f) ? a.z : 0.01f * a.z;
            a.w = al.w + ar.w; a.w = (a.w >= 0.f) ? a.w : 0.01f * a.w;
            __stcs(reinterpret_cast<float4*>(out_alpha + (base + lane) * HEADS), a);
        }
    }
}

// ---------------------------------------------------------------------------
// Launch
// ---------------------------------------------------------------------------
extern "C" void kernel_launch(void* const* d_in, const int* in_sizes, int n_in,
                              void* d_out, int out_size)
{
    const float* x     = (const float*)d_in[0];   // [N, 128]
    const float* W     = (const float*)d_in[1];   // [128, 128]
    const float* b     = (const float*)d_in[2];   // [128]
    const float* att_l = (const float*)d_in[3];   // [1,4,32] -> flat 128
    const float* att_r = (const float*)d_in[4];   // [1,4,32] -> flat 128
    const int*   src   = (const int*)d_in[5];     // [E]
    const int*   trg   = (const int*)d_in[6];     // [E]

    float* out_alpha = (float*)d_out;                                   // [E, 4]
    float* out_x     = (float*)d_out + (size_t)N_EDGES * HEADS;         // [E, 4, 32]

    // 1) projection GEMM into g_h (+ fused alpha_l/alpha_r)
    int gemm_blocks = (N_NODES + BM - 1) / BM;                 // 782
    gemm_proj_kernel<<<gemm_blocks, 256>>>(x, W, b, att_l, att_r, N_NODES);

    // 2) edge lift: persistent, 5 CTAs/SM, grid-stride
    int edge_blocks = 148 * 5;                                 // 740
    edge_lift_kernel<<<edge_blocks, 256>>>(src, trg, out_alpha, out_x, N_EDGES);
}

// round 13
// speedup vs baseline: 1.0961x; 1.0961x over previous
#include <cuda_runtime.h>
#include <cuda_bf16.h>
#include <cstdint>

// Problem constants
#define N_NODES 100000
#define N_EDGES 1638400
#define IN_CH   128
#define HEADS   4
#define OUT_CH  32
#define OUTF    (HEADS * OUT_CH)   // 128

// Scratch (allowed: __device__ globals, no allocation)
__device__ float g_h [(size_t)N_NODES * OUTF];   // 51.2 MB, L2-resident
__device__ float g_al[(size_t)N_NODES * HEADS];
__device__ float g_ar[(size_t)N_NODES * HEADS];

// ===========================================================================
// Kernel 1: h = x @ W^T + b via mma.sync bf16 3-term split (sm_80+ HMMA path;
// tcgen05 rejected by harness ptxas targeting plain sm_103).
//   h = x_hi*W_hi + x_hi*W_lo + x_lo*W_hi  (fp32 accumulate)
// CTA: 128 rows x 128 cols, full K=128 resident in smem bf16 tiles.
// 8 warps; warp tile 64x32 = 4x4 grid of m16n8k16 fragments.
// Epilogue stages D in smem, fuses bias + alpha_l/alpha_r dots.
// ===========================================================================
#define GBM 128
#define ASTR 272            // bf16 tile row stride in bytes (136 bf16) — conflict-free
#define TILE_BYTES (128 * ASTR)   // 34816

// dynamic smem layout (bytes)
#define SO_BIAS 0
#define SO_ATTL 512
#define SO_ATTR 1024
#define SO_AHI  1536
#define SO_ALO  (SO_AHI + TILE_BYTES)
#define SO_WHI  (SO_ALO + TILE_BYTES)
#define SO_WLO  (SO_WHI + TILE_BYTES)
#define GEMM_SMEM_BYTES (SO_WLO + TILE_BYTES)   // 140800
#define DS 132              // D staging row stride (floats), overlays SO_AHI

__device__ __forceinline__ void mma_bf16_16816(float d[4],
                                               uint32_t a0, uint32_t a1,
                                               uint32_t a2, uint32_t a3,
                                               uint32_t b0, uint32_t b1) {
    asm volatile(
        "mma.sync.aligned.m16n8k16.row.col.f32.bf16.bf16.f32 "
        "{%0,%1,%2,%3}, {%4,%5,%6,%7}, {%8,%9}, {%0,%1,%2,%3};"
        : "+f"(d[0]), "+f"(d[1]), "+f"(d[2]), "+f"(d[3])
        : "r"(a0), "r"(a1), "r"(a2), "r"(a3), "r"(b0), "r"(b1));
}

__device__ __forceinline__ uint32_t lds32(const char* p) {
    return *reinterpret_cast<const uint32_t*>(p);
}

__global__ void __launch_bounds__(256)
gat_gemm_hmma(const float* __restrict__ x,
              const float* __restrict__ W,
              const float* __restrict__ b,
              const float* __restrict__ att_l,
              const float* __restrict__ att_r,
              int nrows)
{
    extern __shared__ char smem[];
    const int tid  = threadIdx.x;
    const int row0 = blockIdx.x * GBM;

    // ---- params to smem ----
    if (tid < 128) {
        ((float*)(smem + SO_BIAS))[tid] = b[tid];
        ((float*)(smem + SO_ATTL))[tid] = att_l[tid];
        ((float*)(smem + SO_ATTR))[tid] = att_r[tid];
    }

    // ---- convert x tile and W to bf16 hi/lo (each thread: one (row, half)) ----
    {
        const int row  = tid >> 1;
        const int half = tid & 1;
        const int grow = row0 + row;
        const bool xvalid = (grow < nrows);

        #pragma unroll
        for (int i = 0; i < 8; i++) {
            const int k0 = half * 64 + i * 8;
            // x slice
            float f[8];
            if (xvalid) {
                const float4* p = reinterpret_cast<const float4*>(x + (size_t)grow * IN_CH + k0);
                float4 v0 = p[0], v1 = p[1];
                f[0]=v0.x; f[1]=v0.y; f[2]=v0.z; f[3]=v0.w;
                f[4]=v1.x; f[5]=v1.y; f[6]=v1.z; f[7]=v1.w;
            } else {
                #pragma unroll
                for (int j = 0; j < 8; j++) f[j] = 0.f;
            }
            uint32_t hi[4], lo[4];
            #pragma unroll
            for (int j = 0; j < 4; j++) {
                __nv_bfloat162 h2 = __floats2bfloat162_rn(f[2*j], f[2*j+1]);
                float2 hf = __bfloat1622float2(h2);
                __nv_bfloat162 l2 = __floats2bfloat162_rn(f[2*j] - hf.x, f[2*j+1] - hf.y);
                hi[j] = *reinterpret_cast<uint32_t*>(&h2);
                lo[j] = *reinterpret_cast<uint32_t*>(&l2);
            }
            const int off = row * ASTR + k0 * 2;   // 16B aligned (ASTR=272, k0 mult of 8)
            *reinterpret_cast<uint4*>(smem + SO_AHI + off) = make_uint4(hi[0], hi[1], hi[2], hi[3]);
            *reinterpret_cast<uint4*>(smem + SO_ALO + off) = make_uint4(lo[0], lo[1], lo[2], lo[3]);

            // W slice (row = output channel; always valid)
            const float4* q = reinterpret_cast<const float4*>(W + (size_t)row * IN_CH + k0);
            float4 w0 = q[0], w1 = q[1];
            float g[8] = { w0.x, w0.y, w0.z, w0.w, w1.x, w1.y, w1.z, w1.w };
            #pragma unroll
            for (int j = 0; j < 4; j++) {
                __nv_bfloat162 h2 = __floats2bfloat162_rn(g[2*j], g[2*j+1]);
                float2 hf = __bfloat1622float2(h2);
                __nv_bfloat162 l2 = __floats2bfloat162_rn(g[2*j] - hf.x, g[2*j+1] - hf.y);
                hi[j] = *reinterpret_cast<uint32_t*>(&h2);
                lo[j] = *reinterpret_cast<uint32_t*>(&l2);
            }
            *reinterpret_cast<uint4*>(smem + SO_WHI + off) = make_uint4(hi[0], hi[1], hi[2], hi[3]);
            *reinterpret_cast<uint4*>(smem + SO_WLO + off) = make_uint4(lo[0], lo[1], lo[2], lo[3]);
        }
    }
    __syncthreads();

    // ---- MMA mainloop ----
    const int wid  = tid >> 5;
    const int lane = tid & 31;
    const int wm = (wid & 1) * 64;        // warp m origin
    const int wn = (wid >> 1) * 32;       // warp n origin
    const int gr = lane >> 2;             // 0..7
    const int kq = (lane & 3) * 2;        // 0,2,4,6

    float d[4][4][4];
    #pragma unroll
    for (int mt = 0; mt < 4; mt++)
        #pragma unroll
        for (int nt = 0; nt < 4; nt++)
            #pragma unroll
            for (int e = 0; e < 4; e++) d[mt][nt][e] = 0.f;

    #pragma unroll
    for (int s = 0; s < 3; s++) {
        const char* As = smem + ((s == 2) ? SO_ALO : SO_AHI);
        const char* Bs = smem + ((s == 1) ? SO_WLO : SO_WHI);
        #pragma unroll
        for (int ks = 0; ks < 8; ks++) {
            const int k0 = ks * 16;
            uint32_t a[4][4], bb[4][2];
            #pragma unroll
            for (int mt = 0; mt < 4; mt++) {
                const int m = wm + mt * 16;
                a[mt][0] = lds32(As + (m + gr    ) * ASTR + (k0 + kq    ) * 2);
                a[mt][1] = lds32(As + (m + gr + 8) * ASTR + (k0 + kq    ) * 2);
                a[mt][2] = lds32(As + (m + gr    ) * ASTR + (k0 + kq + 8) * 2);
                a[mt][3] = lds32(As + (m + gr + 8) * ASTR + (k0 + kq + 8) * 2);
            }
            #pragma unroll
            for (int nt = 0; nt < 4; nt++) {
                const int n = wn + nt * 8 + gr;
                bb[nt][0] = lds32(Bs + n * ASTR + (k0 + kq    ) * 2);
                bb[nt][1] = lds32(Bs + n * ASTR + (k0 + kq + 8) * 2);
            }
            #pragma unroll
            for (int mt = 0; mt < 4; mt++)
                #pragma unroll
                for (int nt = 0; nt < 4; nt++)
                    mma_bf16_16816(d[mt][nt], a[mt][0], a[mt][1], a[mt][2], a[mt][3],
                                   bb[nt][0], bb[nt][1]);
        }
    }
    __syncthreads();   // A/W tiles dead; stage D over SO_AHI region

    float* Dst = (float*)(smem + SO_AHI);   // [128][DS]
    #pragma unroll
    for (int mt = 0; mt < 4; mt++) {
        #pragma unroll
        for (int nt = 0; nt < 4; nt++) {
            const int r = wm + mt * 16 + gr;
            const int c = wn + nt * 8 + kq;
            *reinterpret_cast<float2*>(Dst + r * DS + c)       = make_float2(d[mt][nt][0], d[mt][nt][1]);
            *reinterpret_cast<float2*>(Dst + (r + 8) * DS + c) = make_float2(d[mt][nt][2], d[mt][nt][3]);
        }
    }
    __syncthreads();

    // ---- epilogue: thread = (row, half); bias add, g_h store, alpha dots ----
    {
        const int row  = tid >> 1;
        const int half = tid & 1;
        const int grow = row0 + row;
        if (grow < nrows) {
            const float* sbias = (const float*)(smem + SO_BIAS);
            const float* sattl = (const float*)(smem + SO_ATTL);
            const float* sattr = (const float*)(smem + SO_ATTR);
            float sl0 = 0.f, sr0 = 0.f, sl1 = 0.f, sr1 = 0.f;
            #pragma unroll
            for (int q = 0; q < 16; q++) {         // 16 float4 chunks = 64 cols
                float4 v;
                float* vp = &v.x;
                #pragma unroll
                for (int e = 0; e < 4; e++) {
                    const int gc = half * 64 + q * 4 + e;
                    float val = Dst[row * DS + gc] + sbias[gc];
                    vp[e] = val;
                    if (q < 8) { sl0 += val * sattl[gc]; sr0 += val * sattr[gc]; }
                    else       { sl1 += val * sattl[gc]; sr1 += val * sattr[gc]; }
                }
                *reinterpret_cast<float4*>(g_h + (size_t)grow * OUTF + half * 64 + q * 4) = v;
            }
            const int h0 = half * 2;
            *reinterpret_cast<float2*>(g_al + (size_t)grow * HEADS + h0) = make_float2(sl0, sl1);
            *reinterpret_cast<float2*>(g_ar + (size_t)grow * HEADS + h0) = make_float2(sr0, sr1);
        }
    }
}

// ===========================================================================
// Kernel 2: edge lift — exact R10 configuration (measured 186.7us):
// persistent grid-stride, 8 edges/warp/iter, plain __ldg gathers,
// __ldcs index loads, .cs streaming output stores, 4 CTAs/SM.
// ===========================================================================
#define EPW 8   // edges per warp per iteration (N_EDGES % EPW == 0)

__global__ void __launch_bounds__(256, 4)
edge_lift_kernel(const int* __restrict__ src_idx,
                 const int* __restrict__ trg_idx,
                 float* __restrict__ out_alpha,
                 float* __restrict__ out_x,
                 int nedges)
{
    const int lane   = threadIdx.x & 31;
    const int nwarps = (gridDim.x * blockDim.x) >> 5;
    const int gw     = (blockIdx.x * blockDim.x + threadIdx.x) >> 5;

    for (long long base = (long long)gw * EPW; base < nedges;
         base += (long long)nwarps * EPW) {

        int sidx = 0, tidx = 0;
        if (lane < EPW) {
            sidx = __ldcs(src_idx + base + lane);   // streaming: read-once
            tidx = __ldcs(trg_idx + base + lane);
        }

        int s[EPW];
        #pragma unroll
        for (int u = 0; u < EPW; u++)
            s[u] = __shfl_sync(0xffffffffu, sidx, u);

        // EPW independent gathers (MLP=EPW), L2-resident g_h
        float4 v[EPW];
        #pragma unroll
        for (int u = 0; u < EPW; u++)
            v[u] = *reinterpret_cast<const float4*>(g_h + (size_t)s[u] * OUTF + lane * 4);

        #pragma unroll
        for (int u = 0; u < EPW; u++)
            __stcs(reinterpret_cast<float4*>(out_x + (base + u) * OUTF + lane * 4), v[u]);

        if (lane < EPW) {
            float4 al = *reinterpret_cast<const float4*>(g_al + (size_t)sidx * HEADS);
            float4 ar = *reinterpret_cast<const float4*>(g_ar + (size_t)tidx * HEADS);
            float4 a;
            a.x = al.x + ar.x; a.x = (a.x >= 0.f) ? a.x : 0.01f * a.x;
            a.y = al.y + ar.y; a.y = (a.y >= 0.f) ? a.y : 0.01f * a.y;
            a.z = al.z + ar.z; a.z = (a.z >= 0.f) ? a.z : 0.01f * a.z;
            a.w = al.w + ar.w; a.w = (a.w >= 0.f) ? a.w : 0.01f * a.w;
            __stcs(reinterpret_cast<float4*>(out_alpha + (base + lane) * HEADS), a);
        }
    }
}

// ---------------------------------------------------------------------------
// Launch
// ---------------------------------------------------------------------------
extern "C" void kernel_launch(void* const* d_in, const int* in_sizes, int n_in,
                              void* d_out, int out_size)
{
    const float* x     = (const float*)d_in[0];   // [N, 128]
    const float* W     = (const float*)d_in[1];   // [128, 128]
    const float* b     = (const float*)d_in[2];   // [128]
    const float* att_l = (const float*)d_in[3];   // [1,4,32] -> flat 128
    const float* att_r = (const float*)d_in[4];   // [1,4,32] -> flat 128
    const int*   src   = (const int*)d_in[5];     // [E]
    const int*   trg   = (const int*)d_in[6];     // [E]

    float* out_alpha = (float*)d_out;                                   // [E, 4]
    float* out_x     = (float*)d_out + (size_t)N_EDGES * HEADS;         // [E, 4, 32]

    // >48KB dynamic smem opt-in (idempotent; harmless outside capture)
    cudaFuncSetAttribute(gat_gemm_hmma,
                         cudaFuncAttributeMaxDynamicSharedMemorySize,
                         GEMM_SMEM_BYTES);

    // 1) HMMA projection GEMM into g_h (+ fused alpha_l/alpha_r)
    int gemm_blocks = (N_NODES + GBM - 1) / GBM;               // 782
    gat_gemm_hmma<<<gemm_blocks, 256, GEMM_SMEM_BYTES>>>(x, W, b, att_l, att_r, N_NODES);

    // 2) edge lift: persistent, 4 CTAs/SM, grid-stride (R10 config)
    int edge_blocks = 148 * 4;                                 // 592
    edge_lift_kernel<<<edge_blocks, 256>>>(src, trg, out_alpha, out_x, N_EDGES);
}